// round 5
// baseline (speedup 1.0000x reference)
#include <cuda_runtime.h>
#include <math.h>

// IDM_43748536877069  — B=8, NV=2048 pairwise IDM leader search + epilogue.
//
// Rotated-frame cone test (exact):
//   u = dx*cos(psi_j) + dy*sin(psi_j);  w = -dx*sin(psi_j) + dy*cos(psi_j)
//   cone ⟺ |w|*cot(20°) < u      (implies u>0; dx=dy=0 -> false)
// dx,dy computed explicitly (self-pair exactly (0,0), never selected).
//
// R5: packed fp32 (f32x2 -> FADD2/FMUL2/FFMA2) halves the fma-pipe op count.
// SoA float4 staging; 4 per-slot accumulators so argmin tracking is 1 SEL.

#define NV 2048
#define SLOTS 112                      // egos per block
#define SUBS 8                         // candidate-split per ego
#define THREADS (SLOTS * SUBS)         // 896
#define QUADS (NV / 4)                 // 512 candidate quads
#define QCHUNK (QUADS / SUBS)          // 64 quads per thread
#define BPB ((NV + SLOTS - 1) / SLOTS) // 19 blocks per batch

typedef unsigned long long ull;

__device__ __forceinline__ ull pk2(float lo, float hi) {
    ull r; asm("mov.b64 %0, {%1, %2};" : "=l"(r) : "f"(lo), "f"(hi)); return r;
}
__device__ __forceinline__ float2 upk2(ull v) {
    float2 f; asm("mov.b64 {%0, %1}, %2;" : "=f"(f.x), "=f"(f.y) : "l"(v)); return f;
}
__device__ __forceinline__ ull add2(ull a, ull b) {
    ull r; asm("add.rn.f32x2 %0, %1, %2;" : "=l"(r) : "l"(a), "l"(b)); return r;
}
__device__ __forceinline__ ull mul2(ull a, ull b) {
    ull r; asm("mul.rn.f32x2 %0, %1, %2;" : "=l"(r) : "l"(a), "l"(b)); return r;
}
__device__ __forceinline__ ull fma2(ull a, ull b, ull c) {
    ull r; asm("fma.rn.f32x2 %0, %1, %2, %3;" : "=l"(r) : "l"(a), "l"(b), "l"(c)); return r;
}

__global__ __launch_bounds__(THREADS, 1)
void idm_kernel(const float* __restrict__ state,
                const float* __restrict__ lengths,
                const float* __restrict__ v0p,
                const float* __restrict__ s0p,
                const float* __restrict__ dthp,
                const float* __restrict__ amaxp,
                const float* __restrict__ bp,
                float* __restrict__ out)
{
    __shared__ float4 x4[QUADS];             // 8 KB: x of candidates 4q..4q+3
    __shared__ float4 y4[QUADS];             // 8 KB
    __shared__ float  pval[SUBS][SLOTS];     // 3.5 KB
    __shared__ int    pidx[SUBS][SLOTS];     // 3.5 KB

    const int b       = blockIdx.x / BPB;
    const int egoBase = (blockIdx.x % BPB) * SLOTS;
    const float* st   = state + (size_t)b * NV * 5;

    // Stage candidate positions, SoA packed 4 per float4.
    for (int q = threadIdx.x; q < QUADS; q += THREADS) {
        const float* a = st + (4 * q) * 5;
        x4[q] = make_float4(a[0], a[5], a[10], a[15]);
        y4[q] = make_float4(a[1], a[6], a[11], a[16]);
    }
    __syncthreads();

    const int sub = threadIdx.x & 7;
    const int e   = threadIdx.x >> 3;
    const int j   = egoBase + e;
    const bool valid = (j < NV);
    const int jc  = valid ? j : 0;

    // ego position read from the same staged values (bitwise identical source)
    const float4 xq = x4[jc >> 2];
    const float4 yq = y4[jc >> 2];
    const int jr = jc & 3;
    const float xj = (jr == 0) ? xq.x : (jr == 1) ? xq.y : (jr == 2) ? xq.z : xq.w;
    const float yj = (jr == 0) ? yq.x : (jr == 1) ? yq.y : (jr == 2) ? yq.z : yq.w;
    const float psj = __ldg(st + jc * 5 + 3);
    float sj, cjv;
    sincosf(psj, &sj, &cjv);

    const float COT20 = 2.7474774194546225f;   // 1/tan(20 deg)
    const float scj = cjv * COT20;
    const float nsj = -sj * COT20;

    const ull nx2 = pk2(-xj, -xj);
    const ull ny2 = pk2(-yj, -yj);
    const ull c2  = pk2(cjv, cjv);
    const ull s2  = pk2(sj, sj);
    const ull sc2 = pk2(scj, scj);
    const ull ns2 = pk2(nsj, nsj);

    const float INF = __int_as_float(0x7f800000);
    float b0 = INF, b1 = INF, b2 = INF, b3 = INF;   // per-slot running min
    int   p0 = 0,  p1 = 0,  p2 = 0,  p3 = 0;        // quad index of each min

    if (valid) {
        #pragma unroll 2
        for (int t = 0; t < QCHUNK; ++t) {
            const int p = (t << 3) + sub;            // quad index, p ≡ sub (mod 8)
            const float4 X = x4[p];                   // LDS.128
            const float4 Y = y4[p];                   // LDS.128

            const ull DX01 = add2(pk2(X.x, X.y), nx2);
            const ull DX23 = add2(pk2(X.z, X.w), nx2);
            const ull DY01 = add2(pk2(Y.x, Y.y), ny2);
            const ull DY23 = add2(pk2(Y.z, Y.w), ny2);

            const ull U01 = fma2(DX01, c2,  mul2(DY01, s2));
            const ull U23 = fma2(DX23, c2,  mul2(DY23, s2));
            const ull W01 = fma2(DY01, sc2, mul2(DX01, ns2));
            const ull W23 = fma2(DY23, sc2, mul2(DX23, ns2));

            const float2 u01 = upk2(U01), u23 = upk2(U23);
            const float2 w01 = upk2(W01), w23 = upk2(W23);

            bool ok;
            ok = (fabsf(w01.x) < u01.x) && (u01.x < b0); b0 = ok ? u01.x : b0; p0 = ok ? p : p0;
            ok = (fabsf(w01.y) < u01.y) && (u01.y < b1); b1 = ok ? u01.y : b1; p1 = ok ? p : p1;
            ok = (fabsf(w23.x) < u23.x) && (u23.x < b2); b2 = ok ? u23.x : b2; p2 = ok ? p : p2;
            ok = (fabsf(w23.y) < u23.y) && (u23.y < b3); b3 = ok ? u23.y : b3; p3 = ok ? p : p3;
        }
    }

    // merge 4 slot accumulators (value, then lower index on tie)
    float bv = b0;  int bx = (p0 << 2);
    {
        const int i1 = (p1 << 2) | 1;
        if (b1 < bv || (b1 == bv && i1 < bx)) { bv = b1; bx = i1; }
        const int i2 = (p2 << 2) | 2;
        if (b2 < bv || (b2 == bv && i2 < bx)) { bv = b2; bx = i2; }
        const int i3 = (p3 << 2) | 3;
        if (b3 < bv || (b3 == bv && i3 < bx)) { bv = b3; bx = i3; }
    }
    pval[sub][e] = bv;
    pidx[sub][e] = bx;
    __syncthreads();

    // One thread per ego: 8-way combine (tie -> lower index) + IDM epilogue.
    if (threadIdx.x < SLOTS) {
        const int ee = threadIdx.x;
        const int jj = egoBase + ee;
        if (jj < NV) {
            float fbv = pval[0][ee];
            int   fbx = pidx[0][ee];
            #pragma unroll
            for (int s = 1; s < SUBS; ++s) {
                const float v2 = pval[s][ee];
                const int   i2 = pidx[s][ee];
                if (v2 < fbv || (v2 == fbv && i2 < fbx)) { fbv = v2; fbx = i2; }
            }

            const float v0   = v0p[0];
            const float s0   = s0p[0];
            const float dth  = dthp[0];
            const float amax = amaxp[0];
            const float bb   = bp[0];

            const float vje  = __ldg(st + jj * 5 + 2);
            const float psje = __ldg(st + jj * 5 + 3);
            float sje, cje;
            sincosf(psje, &sje, &cje);

            const float q  = vje / v0;
            const float q2 = q * q;
            const float afree = amax * (1.0f - q2 * q2);

            float action = afree;
            const float sal = fbv - lengths[jj];
            if (isfinite(sal)) {
                const float vl  = __ldg(st + fbx * 5 + 2);
                const float psl = __ldg(st + fbx * 5 + 3);
                float sl, cl;
                sincosf(psl, &sl, &cl);
                const float dvx = vl * cl - vje * cje;
                const float dvy = vl * sl - vje * sje;
                const float ndv = fmaf(dvx, cje, dvy * sje);

                const float sstar = s0 + vje * dth
                                  + vje * ndv / (2.0f * sqrtf(amax * bb));
                const float r = sstar / sal;
                action = afree - amax * r * r;
            }
            out[(size_t)b * NV + jj] = action;
        }
    }
}

extern "C" void kernel_launch(void* const* d_in, const int* in_sizes, int n_in,
                              void* d_out, int out_size) {
    const float* state   = (const float*)d_in[0];
    const float* lengths = (const float*)d_in[1];
    const float* v0      = (const float*)d_in[2];
    const float* s0      = (const float*)d_in[3];
    const float* dth     = (const float*)d_in[4];
    const float* amax    = (const float*)d_in[5];
    const float* bpar    = (const float*)d_in[6];
    float* out = (float*)d_out;

    const int B = in_sizes[0] / (NV * 5);
    const int grid = B * BPB;    // 8 * 19 = 152 == #SMs on GB300
    idm_kernel<<<grid, THREADS>>>(state, lengths, v0, s0, dth, amax, bpar, out);
}

// round 6
// speedup vs baseline: 1.0152x; 1.0152x over previous
#include <cuda_runtime.h>
#include <math.h>

// IDM_43748536877069  — B=8, NV=2048 pairwise IDM leader search + epilogue.
//
// Rotated-frame cone test (exact equivalence):
//   u = dx*cos(psi_j) + dy*sin(psi_j)    (longitudinal)
//   w = -dx*sin(psi_j) + dy*cos(psi_j)   (lateral)
//   cone ⟺ |w|*cot(20°) < u             (implies u>0; dx=dy=0 -> false)
// dx,dy computed explicitly so the self-pair is exactly (0,0) -> never leader.
//
// R6: R4 + dual argmin accumulators (even/odd candidate of each float4) to
// break the FSETP->SEL serial chain; unroll 4. fma-pipe floor ~12 cyc/cand.

#define NV 2048
#define SLOTS 112                      // egos per block
#define SUBS 8                         // candidate-split per ego
#define THREADS (SLOTS * SUBS)         // 896
#define PAIRS (NV / 2)                 // 1024 float4-packed candidate pairs
#define PCHUNK (PAIRS / SUBS)          // 128 pairs per thread
#define BPB ((NV + SLOTS - 1) / SLOTS) // 19 blocks per batch

__global__ __launch_bounds__(THREADS, 1)
void idm_kernel(const float* __restrict__ state,
                const float* __restrict__ lengths,
                const float* __restrict__ v0p,
                const float* __restrict__ s0p,
                const float* __restrict__ dthp,
                const float* __restrict__ amaxp,
                const float* __restrict__ bp,
                float* __restrict__ out)
{
    __shared__ float4 xy4[PAIRS];            // 16 KB: (x0,y0,x1,y1) per pair
    __shared__ float  pval[SUBS][SLOTS];     // 3.5 KB
    __shared__ int    pidx[SUBS][SLOTS];     // 3.5 KB

    const int b       = blockIdx.x / BPB;
    const int egoBase = (blockIdx.x % BPB) * SLOTS;
    const float* st   = state + (size_t)b * NV * 5;

    // Stage candidate positions, packed two per float4.
    for (int p = threadIdx.x; p < PAIRS; p += THREADS) {
        const float* a = st + (2 * p) * 5;
        xy4[p] = make_float4(a[0], a[1], a[5], a[6]);
    }
    __syncthreads();

    // lane mapping: sub = tid&7, ego slot e = tid>>3.
    // A warp = 4 egos x 8 subs; loop loads xy4[8t+sub] -> 8 consecutive
    // float4 smem addresses per warp (128B, conflict-free, 4-lane broadcast).
    const int sub = threadIdx.x & 7;
    const int e   = threadIdx.x >> 3;
    const int j   = egoBase + e;
    const bool valid = (j < NV);
    const int jc  = valid ? j : 0;

    const float4 cj0 = xy4[jc >> 1];
    const float xj = (jc & 1) ? cj0.z : cj0.x;
    const float yj = (jc & 1) ? cj0.w : cj0.y;
    const float psj = __ldg(st + jc * 5 + 3);
    float sj, cjv;
    sincosf(psj, &sj, &cjv);

    const float COT20 = 2.7474774194546225f;   // 1/tan(20 deg)
    const float scj = cjv * COT20;
    const float nsj = -sj * COT20;

    const float INF = __int_as_float(0x7f800000);
    // Independent accumulators: slot0 = even candidate (i=2p), slot1 = odd (2p+1).
    float b0 = INF, b1 = INF;
    int   q0 = 0,   q1 = 0;     // pair index of each running min

    if (valid) {
        #pragma unroll 4
        for (int t = 0; t < PCHUNK; ++t) {
            const int p = (t << 3) + sub;        // pair index, p ≡ sub (mod 8)
            const float4 c = xy4[p];

            // even candidate (i = 2p)
            const float dx0 = c.x - xj;
            const float dy0 = c.y - yj;
            const float u0  = fmaf(dx0, cjv, dy0 * sj);
            const float w0  = fmaf(dy0, scj, dx0 * nsj);
            // odd candidate (i = 2p+1)
            const float dx1 = c.z - xj;
            const float dy1 = c.w - yj;
            const float u1  = fmaf(dx1, cjv, dy1 * sj);
            const float w1  = fmaf(dy1, scj, dx1 * nsj);

            const bool ok0 = (fabsf(w0) < u0) && (u0 < b0);
            b0 = ok0 ? u0 : b0;
            q0 = ok0 ? p  : q0;
            const bool ok1 = (fabsf(w1) < u1) && (u1 < b1);
            b1 = ok1 ? u1 : b1;
            q1 = ok1 ? p  : q1;
        }
    }

    // Merge even/odd slots: value first, then lower index on tie.
    float bv = b0;
    int   bx = (q0 << 1);
    {
        const int i1 = (q1 << 1) | 1;
        if (b1 < bv || (b1 == bv && i1 < bx)) { bv = b1; bx = i1; }
    }
    pval[sub][e] = bv;
    pidx[sub][e] = bx;
    __syncthreads();

    // One thread per ego: 8-way combine (tie -> lower index) + IDM epilogue.
    if (threadIdx.x < SLOTS) {
        const int ee = threadIdx.x;
        const int jj = egoBase + ee;
        if (jj < NV) {
            float fbv = pval[0][ee];
            int   fbx = pidx[0][ee];
            #pragma unroll
            for (int s = 1; s < SUBS; ++s) {
                const float v2 = pval[s][ee];
                const int   i2 = pidx[s][ee];
                if (v2 < fbv || (v2 == fbv && i2 < fbx)) { fbv = v2; fbx = i2; }
            }

            const float v0   = v0p[0];
            const float s0   = s0p[0];
            const float dth  = dthp[0];
            const float amax = amaxp[0];
            const float bb   = bp[0];

            const float vje  = __ldg(st + jj * 5 + 2);
            const float psje = __ldg(st + jj * 5 + 3);
            float sje, cje;
            sincosf(psje, &sje, &cje);

            const float q  = vje / v0;
            const float q2 = q * q;
            const float afree = amax * (1.0f - q2 * q2);

            float action = afree;
            const float sal = fbv - lengths[jj];
            if (isfinite(sal)) {
                const float vl  = __ldg(st + fbx * 5 + 2);
                const float psl = __ldg(st + fbx * 5 + 3);
                float sl, cl;
                sincosf(psl, &sl, &cl);
                const float dvx = vl * cl - vje * cje;
                const float dvy = vl * sl - vje * sje;
                const float ndv = fmaf(dvx, cje, dvy * sje);

                const float sstar = s0 + vje * dth
                                  + vje * ndv / (2.0f * sqrtf(amax * bb));
                const float r = sstar / sal;
                action = afree - amax * r * r;
            }
            out[(size_t)b * NV + jj] = action;
        }
    }
}

extern "C" void kernel_launch(void* const* d_in, const int* in_sizes, int n_in,
                              void* d_out, int out_size) {
    const float* state   = (const float*)d_in[0];
    const float* lengths = (const float*)d_in[1];
    const float* v0      = (const float*)d_in[2];
    const float* s0      = (const float*)d_in[3];
    const float* dth     = (const float*)d_in[4];
    const float* amax    = (const float*)d_in[5];
    const float* bpar    = (const float*)d_in[6];
    float* out = (float*)d_out;

    const int B = in_sizes[0] / (NV * 5);
    const int grid = B * BPB;    // 8 * 19 = 152 == #SMs on GB300
    idm_kernel<<<grid, THREADS>>>(state, lengths, v0, s0, dth, amax, bpar, out);
}

// round 7
// speedup vs baseline: 1.1215x; 1.1047x over previous
#include <cuda_runtime.h>
#include <math.h>

// IDM_43748536877069  — B=8, NV=2048 pairwise IDM leader search + epilogue.
//
// Rotated-frame cone test (exact equivalence):
//   u = dx*cos(psi_j) + dy*sin(psi_j)    (longitudinal)
//   w = -dx*sin(psi_j) + dy*cos(psi_j)   (lateral)
//   cone ⟺ |w|*cot(20°) < u             (implies u>0; dx=dy=0 -> false)
// dx,dy computed explicitly so the self-pair is exactly (0,0) -> never leader.
//
// R7: R4 body (proven fastest: single accumulator, 6 fma + 4 alu per cand)
// with unroll 8 for deeper MLP / latency hiding.

#define NV 2048
#define SLOTS 112                      // egos per block
#define SUBS 8                         // candidate-split per ego
#define THREADS (SLOTS * SUBS)         // 896
#define PAIRS (NV / 2)                 // 1024 float4-packed candidate pairs
#define PCHUNK (PAIRS / SUBS)          // 128 pairs per thread
#define BPB ((NV + SLOTS - 1) / SLOTS) // 19 blocks per batch

__global__ __launch_bounds__(THREADS, 1)
void idm_kernel(const float* __restrict__ state,
                const float* __restrict__ lengths,
                const float* __restrict__ v0p,
                const float* __restrict__ s0p,
                const float* __restrict__ dthp,
                const float* __restrict__ amaxp,
                const float* __restrict__ bp,
                float* __restrict__ out)
{
    __shared__ float4 xy4[PAIRS];            // 16 KB: (x0,y0,x1,y1) per pair
    __shared__ float  pval[SUBS][SLOTS];     // 3.5 KB
    __shared__ int    pidx[SUBS][SLOTS];     // 3.5 KB

    const int b       = blockIdx.x / BPB;
    const int egoBase = (blockIdx.x % BPB) * SLOTS;
    const float* st   = state + (size_t)b * NV * 5;

    // Stage candidate positions, packed two per float4.
    for (int p = threadIdx.x; p < PAIRS; p += THREADS) {
        const float* a = st + (2 * p) * 5;
        xy4[p] = make_float4(a[0], a[1], a[5], a[6]);
    }
    __syncthreads();

    // lane mapping: sub = tid&7, ego slot e = tid>>3.
    // A warp = 4 egos x 8 subs; loop loads xy4[8t+sub] -> 8 consecutive
    // float4 smem addresses per warp (128B, conflict-free, 4-lane broadcast).
    const int sub = threadIdx.x & 7;
    const int e   = threadIdx.x >> 3;
    const int j   = egoBase + e;
    const bool valid = (j < NV);
    const int jc  = valid ? j : 0;

    const float4 cj0 = xy4[jc >> 1];
    const float xj = (jc & 1) ? cj0.z : cj0.x;
    const float yj = (jc & 1) ? cj0.w : cj0.y;
    const float psj = __ldg(st + jc * 5 + 3);
    float sj, cjv;
    sincosf(psj, &sj, &cjv);

    const float COT20 = 2.7474774194546225f;   // 1/tan(20 deg)
    const float scj = cjv * COT20;
    const float nsj = -sj * COT20;

    float best = __int_as_float(0x7f800000);   // +inf
    int   bi   = 0;

    if (valid) {
        #pragma unroll 8
        for (int t = 0; t < PCHUNK; ++t) {
            const int p = (t << 3) + sub;        // pair index, p ≡ sub (mod 8)
            const float4 c = xy4[p];

            // even candidate (i = 2p)
            const float dx0 = c.x - xj;
            const float dy0 = c.y - yj;
            const float u0  = fmaf(dx0, cjv, dy0 * sj);
            const float w0  = fmaf(dy0, scj, dx0 * nsj);
            // odd candidate (i = 2p+1)
            const float dx1 = c.z - xj;
            const float dy1 = c.w - yj;
            const float u1  = fmaf(dx1, cjv, dy1 * sj);
            const float w1  = fmaf(dy1, scj, dx1 * nsj);

            const bool ok0 = (fabsf(w0) < u0) && (u0 < best);
            best = ok0 ? u0 : best;
            bi   = ok0 ? (p << 1) : bi;
            const bool ok1 = (fabsf(w1) < u1) && (u1 < best);
            best = ok1 ? u1 : best;
            bi   = ok1 ? ((p << 1) | 1) : bi;
        }
    }
    pval[sub][e] = best;
    pidx[sub][e] = bi;
    __syncthreads();

    // One thread per ego: 8-way combine (tie -> lower index) + IDM epilogue.
    if (threadIdx.x < SLOTS) {
        const int ee = threadIdx.x;
        const int jj = egoBase + ee;
        if (jj < NV) {
            float fbv = pval[0][ee];
            int   fbx = pidx[0][ee];
            #pragma unroll
            for (int s = 1; s < SUBS; ++s) {
                const float v2 = pval[s][ee];
                const int   i2 = pidx[s][ee];
                if (v2 < fbv || (v2 == fbv && i2 < fbx)) { fbv = v2; fbx = i2; }
            }

            const float v0   = v0p[0];
            const float s0   = s0p[0];
            const float dth  = dthp[0];
            const float amax = amaxp[0];
            const float bb   = bp[0];

            const float vje  = __ldg(st + jj * 5 + 2);
            const float psje = __ldg(st + jj * 5 + 3);
            float sje, cje;
            sincosf(psje, &sje, &cje);

            const float q  = vje / v0;
            const float q2 = q * q;
            const float afree = amax * (1.0f - q2 * q2);

            float action = afree;
            const float sal = fbv - lengths[jj];
            if (isfinite(sal)) {
                const float vl  = __ldg(st + fbx * 5 + 2);
                const float psl = __ldg(st + fbx * 5 + 3);
                float sl, cl;
                sincosf(psl, &sl, &cl);
                const float dvx = vl * cl - vje * cje;
                const float dvy = vl * sl - vje * sje;
                const float ndv = fmaf(dvx, cje, dvy * sje);

                const float sstar = s0 + vje * dth
                                  + vje * ndv / (2.0f * sqrtf(amax * bb));
                const float r = sstar / sal;
                action = afree - amax * r * r;
            }
            out[(size_t)b * NV + jj] = action;
        }
    }
}

extern "C" void kernel_launch(void* const* d_in, const int* in_sizes, int n_in,
                              void* d_out, int out_size) {
    const float* state   = (const float*)d_in[0];
    const float* lengths = (const float*)d_in[1];
    const float* v0      = (const float*)d_in[2];
    const float* s0      = (const float*)d_in[3];
    const float* dth     = (const float*)d_in[4];
    const float* amax    = (const float*)d_in[5];
    const float* bpar    = (const float*)d_in[6];
    float* out = (float*)d_out;

    const int B = in_sizes[0] / (NV * 5);
    const int grid = B * BPB;    // 8 * 19 = 152 == #SMs on GB300
    idm_kernel<<<grid, THREADS>>>(state, lengths, v0, s0, dth, amax, bpar, out);
}